// round 2
// baseline (speedup 1.0000x reference)
#include <cuda_runtime.h>

// Problem constants
#define Bb   8
#define Nn   1024
#define Cc   512
#define Kk   20
#define Mm   64
#define Pp   (Bb * Nn)        // 8192 points
#define CNT1 (Pp * Kk)        // 163840 samples for BN1
#define CNT2 Pp               // 8192 samples for BN2
#define EPS  1e-5f

// Scratch (no cudaMalloc allowed)
__device__ float g_W1p[128 * 512];      // folded W1': rows 0..63 = W1a, 64..127 = W1b - W1a
__device__ float g_y[Pp * 128];         // per-point y1(0:64) | y2(64:128)
__device__ float g_hmax[Pp * 64];
__device__ float g_hmin[Pp * 64];
__device__ float g_part1[256 * 128];    // per-block [sum(64) | sumsq(64)]
__device__ float g_bn1[128];            // scale(64) | bias(64)
__device__ float g_p2s[128 * 512];
__device__ float g_p2q[128 * 512];
__device__ float g_bn2[1024];           // scale(512) | bias(512)

// ---------------------------------------------------------------------------
// K0: fold W1 [64][1024] -> W1' [128][512]
// ---------------------------------------------------------------------------
__global__ void k0_prepw(const float* __restrict__ W1) {
    int i = blockIdx.x * 256 + threadIdx.x;      // 0 .. 65535
    int n = i >> 9, c = i & 511;
    float v;
    if (n < 64) {
        v = W1[n * 1024 + c];
    } else {
        int m = n - 64;
        v = W1[m * 1024 + 512 + c] - W1[m * 1024 + c];
    }
    g_W1p[i] = v;
}

// ---------------------------------------------------------------------------
// K1: y[8192][128] = x[8192][512] @ W1'[128][512]^T
// BM=64, BN=128, BK=16; 256 threads; micro-tile 4x8 (strided by 16)
// ---------------------------------------------------------------------------
__global__ void __launch_bounds__(256) k1_gemm1(const float* __restrict__ x) {
    __shared__ float sx[16][65];     // [kk][pt]
    __shared__ float sw[16][129];    // [kk][nn]
    int tid = threadIdx.x;
    int tx = tid & 15, ty = tid >> 4;
    int p0 = blockIdx.x * 64;

    float acc[4][8];
#pragma unroll
    for (int r = 0; r < 4; r++)
#pragma unroll
        for (int j = 0; j < 8; j++) acc[r][j] = 0.f;

    for (int c0 = 0; c0 < 512; c0 += 16) {
#pragma unroll
        for (int i = 0; i < 4; i++) {
            int e = tid + i * 256;
            sx[e & 15][e >> 4] = x[(p0 + (e >> 4)) * 512 + c0 + (e & 15)];
        }
#pragma unroll
        for (int i = 0; i < 8; i++) {
            int e = tid + i * 256;
            sw[e & 15][e >> 4] = g_W1p[(e >> 4) * 512 + c0 + (e & 15)];
        }
        __syncthreads();
#pragma unroll
        for (int kk = 0; kk < 16; kk++) {
            float a[4], b[8];
#pragma unroll
            for (int r = 0; r < 4; r++) a[r] = sx[kk][ty + 16 * r];
#pragma unroll
            for (int j = 0; j < 8; j++) b[j] = sw[kk][tx + 16 * j];
#pragma unroll
            for (int r = 0; r < 4; r++)
#pragma unroll
                for (int j = 0; j < 8; j++) acc[r][j] += a[r] * b[j];
        }
        __syncthreads();
    }
#pragma unroll
    for (int r = 0; r < 4; r++) {
        int p = p0 + ty + 16 * r;
#pragma unroll
        for (int j = 0; j < 8; j++)
            g_y[p * 128 + tx + 16 * j] = acc[r][j];
    }
}

// ---------------------------------------------------------------------------
// K2: gather over K=20 neighbors: per (p,m) max/min; block-partial sum/sumsq
// 256 threads = 4 slots x 64 channels; 32 points/block; grid = 256
// ---------------------------------------------------------------------------
__global__ void __launch_bounds__(256) k2_gather(const int* __restrict__ idx) {
    __shared__ int   sidx[4][20];
    __shared__ float red[2][256];
    int tid = threadIdx.x;
    int m = tid & 63, slot = tid >> 6;
    float fs = 0.f, fq = 0.f;
    int pbase = blockIdx.x * 32;

    for (int i = 0; i < 8; i++) {
        int p = pbase + i * 4 + slot;
        if (m < 20) sidx[slot][m] = idx[p * 20 + m];
        __syncthreads();
        float y2 = g_y[p * 128 + 64 + m];
        int rowb = (p & ~1023) * 128;     // batch base row * 128
        float vmax = -1e30f, vmin = 1e30f;
#pragma unroll
        for (int k = 0; k < 20; k++) {
            int g = sidx[slot][k];
            float v = g_y[rowb + g * 128 + m] + y2;
            fs += v;
            fq += v * v;
            vmax = fmaxf(vmax, v);
            vmin = fminf(vmin, v);
        }
        g_hmax[p * 64 + m] = vmax;
        g_hmin[p * 64 + m] = vmin;
        __syncthreads();
    }
    red[0][tid] = fs;
    red[1][tid] = fq;
    __syncthreads();
    if (tid < 64) {
        float s = red[0][tid] + red[0][tid + 64] + red[0][tid + 128] + red[0][tid + 192];
        float q = red[1][tid] + red[1][tid + 64] + red[1][tid + 128] + red[1][tid + 192];
        g_part1[blockIdx.x * 128 + tid] = s;
        g_part1[blockIdx.x * 128 + 64 + tid] = q;
    }
}

// ---------------------------------------------------------------------------
// K3: finalize BN1 scale/bias
// ---------------------------------------------------------------------------
__global__ void k3_stats1(const float* __restrict__ gamma1, const float* __restrict__ beta1) {
    int m = threadIdx.x;  // 64 threads
    float s = 0.f, q = 0.f;
    for (int i = 0; i < 256; i++) {
        s += g_part1[i * 128 + m];
        q += g_part1[i * 128 + 64 + m];
    }
    float inv = 1.f / (float)CNT1;
    float mu = s * inv;
    float var = q * inv - mu * mu;
    float sc = gamma1[m] * rsqrtf(var + EPS);
    g_bn1[m] = sc;
    g_bn1[64 + m] = beta1[m] - mu * sc;
}

// ---------------------------------------------------------------------------
// K4: v = leaky(bn1(select(max/min))) fused into GEMM2:
//     out[p][d] = sum_m v[p][m] * W2[d][m];  + BN2 partial stats.
// BM=64 pts, BN=64 d, K=64 full; 256 threads; micro 4x4 strided by 16
// ---------------------------------------------------------------------------
__global__ void __launch_bounds__(256) k4_gemm2(const float* __restrict__ W2,
                                                float* __restrict__ out) {
    __shared__ float sh[64][65];   // [m][pt]
    __shared__ float sw[64][65];   // [m][dd]
    __shared__ float sbn[128];
    __shared__ float reds[16 * 64];
    __shared__ float redq[16 * 64];
    int tid = threadIdx.x;
    int tx = tid & 15, ty = tid >> 4;
    int d0 = blockIdx.x * 64, p0 = blockIdx.y * 64;

    if (tid < 128) sbn[tid] = g_bn1[tid];
    __syncthreads();

#pragma unroll
    for (int i = 0; i < 16; i++) {
        int e = tid + i * 256;
        int pt = e >> 6, m = e & 63;
        float sc = sbn[m], bi = sbn[64 + m];
        float h = (sc >= 0.f) ? g_hmax[(p0 + pt) * 64 + m] : g_hmin[(p0 + pt) * 64 + m];
        float v = sc * h + bi;
        sh[m][pt] = fmaxf(v, 0.2f * v);           // leaky
    }
#pragma unroll
    for (int i = 0; i < 16; i++) {
        int e = tid + i * 256;
        int dd = e >> 6, m = e & 63;
        sw[m][dd] = W2[(d0 + dd) * 64 + m];
    }
    __syncthreads();

    float acc[4][4];
#pragma unroll
    for (int r = 0; r < 4; r++)
#pragma unroll
        for (int j = 0; j < 4; j++) acc[r][j] = 0.f;

#pragma unroll
    for (int kk = 0; kk < 64; kk++) {
        float a[4], b[4];
#pragma unroll
        for (int r = 0; r < 4; r++) a[r] = sh[kk][ty + 16 * r];
#pragma unroll
        for (int j = 0; j < 4; j++) b[j] = sw[kk][tx + 16 * j];
#pragma unroll
        for (int r = 0; r < 4; r++)
#pragma unroll
            for (int j = 0; j < 4; j++) acc[r][j] += a[r] * b[j];
    }

    float ps[4] = {0.f, 0.f, 0.f, 0.f}, pq[4] = {0.f, 0.f, 0.f, 0.f};
#pragma unroll
    for (int r = 0; r < 4; r++) {
        int p = p0 + ty + 16 * r;
#pragma unroll
        for (int j = 0; j < 4; j++) {
            float v = acc[r][j];
            out[p * 512 + d0 + tx + 16 * j] = v;
            ps[j] += v;
            pq[j] += v * v;
        }
    }
#pragma unroll
    for (int j = 0; j < 4; j++) {
        reds[ty * 64 + tx + 16 * j] = ps[j];
        redq[ty * 64 + tx + 16 * j] = pq[j];
    }
    __syncthreads();
    if (tid < 64) {
        float s = 0.f, q = 0.f;
#pragma unroll
        for (int t = 0; t < 16; t++) {
            s += reds[t * 64 + tid];
            q += redq[t * 64 + tid];
        }
        g_p2s[blockIdx.y * 512 + d0 + tid] = s;
        g_p2q[blockIdx.y * 512 + d0 + tid] = q;
    }
}

// ---------------------------------------------------------------------------
// K5: finalize BN2
// ---------------------------------------------------------------------------
__global__ void k5_stats2(const float* __restrict__ gamma2, const float* __restrict__ beta2) {
    int d = blockIdx.x * 256 + threadIdx.x;   // 512 total
    float s = 0.f, q = 0.f;
    for (int i = 0; i < 128; i++) {
        s += g_p2s[i * 512 + d];
        q += g_p2q[i * 512 + d];
    }
    float inv = 1.f / (float)CNT2;
    float mu = s * inv;
    float var = q * inv - mu * mu;
    float sc = gamma2[d] * rsqrtf(var + EPS);
    g_bn2[d] = sc;
    g_bn2[512 + d] = beta2[d] - mu * sc;
}

// ---------------------------------------------------------------------------
// K6: in-place affine + leaky on out (float4 vectorized)
// ---------------------------------------------------------------------------
__global__ void __launch_bounds__(256) k6_final(float* __restrict__ out) {
    int i = blockIdx.x * 256 + threadIdx.x;   // float4 index, 1048576 total
    float4 v = reinterpret_cast<float4*>(out)[i];
    int d = (i * 4) & 511;
    float s0 = g_bn2[d],       s1 = g_bn2[d + 1],   s2 = g_bn2[d + 2],   s3 = g_bn2[d + 3];
    float b0 = g_bn2[512 + d], b1 = g_bn2[513 + d], b2 = g_bn2[514 + d], b3 = g_bn2[515 + d];
    float t0 = s0 * v.x + b0;
    float t1 = s1 * v.y + b1;
    float t2 = s2 * v.z + b2;
    float t3 = s3 * v.w + b3;
    v.x = fmaxf(t0, 0.2f * t0);
    v.y = fmaxf(t1, 0.2f * t1);
    v.z = fmaxf(t2, 0.2f * t2);
    v.w = fmaxf(t3, 0.2f * t3);
    reinterpret_cast<float4*>(out)[i] = v;
}

// ---------------------------------------------------------------------------
extern "C" void kernel_launch(void* const* d_in, const int* in_sizes, int n_in,
                              void* d_out, int out_size) {
    const float* x      = (const float*)d_in[0];
    const int*   idx    = (const int*)  d_in[1];
    const float* W1     = (const float*)d_in[2];
    const float* gamma1 = (const float*)d_in[3];
    const float* beta1  = (const float*)d_in[4];
    const float* W2     = (const float*)d_in[5];
    const float* gamma2 = (const float*)d_in[6];
    const float* beta2  = (const float*)d_in[7];
    float* out = (float*)d_out;

    k0_prepw<<<256, 256>>>(W1);
    k1_gemm1<<<128, 256>>>(x);
    k2_gather<<<256, 256>>>(idx);
    k3_stats1<<<1, 64>>>(gamma1, beta1);
    k4_gemm2<<<dim3(8, 128), 256>>>(W2, out);
    k5_stats2<<<2, 256>>>(gamma2, beta2);
    k6_final<<<4096, 256>>>(out);
}

// round 3
// speedup vs baseline: 1.2340x; 1.2340x over previous
#include <cuda_runtime.h>
#include <cstdint>

// Problem constants
#define Bb   8
#define Nn   1024
#define Cc   512
#define Kk   20
#define Mm   64
#define Pp   (Bb * Nn)        // 8192 points
#define CNT1 (Pp * Kk)        // 163840 samples for BN1
#define CNT2 Pp               // 8192 samples for BN2
#define EPS  1e-5f

// Scratch (no cudaMalloc allowed)
__device__ float g_W1hi[128 * 512];     // tf32-hi of folded W1'
__device__ float g_W1lo[128 * 512];     // tf32-lo of folded W1'
__device__ float g_y[Pp * 128];         // per-point y1(0:64) | y2(64:128)
__device__ float g_hmax[Pp * 64];
__device__ float g_hmin[Pp * 64];
__device__ float g_part1[256 * 128];    // per-block [sum(64) | sumsq(64)]
__device__ float g_bn1[128];            // scale(64) | bias(64)
__device__ float g_p2s[128 * 512];
__device__ float g_p2q[128 * 512];
__device__ float g_bn2[1024];           // scale(512) | bias(512)

__device__ __forceinline__ float tf32_rna(float v) {
    uint32_t u;
    asm("cvt.rna.tf32.f32 %0, %1;" : "=r"(u) : "f"(v));
    return __uint_as_float(u);
}

__device__ __forceinline__ void mma_tf32(float* d, const float* a, const float* b) {
    asm volatile(
        "mma.sync.aligned.m16n8k8.row.col.f32.tf32.tf32.f32 "
        "{%0,%1,%2,%3}, {%4,%5,%6,%7}, {%8,%9}, {%0,%1,%2,%3};"
        : "+f"(d[0]), "+f"(d[1]), "+f"(d[2]), "+f"(d[3])
        : "r"(__float_as_uint(a[0])), "r"(__float_as_uint(a[1])),
          "r"(__float_as_uint(a[2])), "r"(__float_as_uint(a[3])),
          "r"(__float_as_uint(b[0])), "r"(__float_as_uint(b[1])));
}

// ---------------------------------------------------------------------------
// K0: fold W1 [64][1024] -> W1' [128][512], split into tf32 hi/lo
// ---------------------------------------------------------------------------
__global__ void k0_prepw(const float* __restrict__ W1) {
    int i = blockIdx.x * 256 + threadIdx.x;      // 0 .. 65535
    int n = i >> 9, c = i & 511;
    float v;
    if (n < 64) {
        v = W1[n * 1024 + c];
    } else {
        int m = n - 64;
        v = W1[m * 1024 + 512 + c] - W1[m * 1024 + c];
    }
    float hi = tf32_rna(v);
    float lo = tf32_rna(v - hi);
    g_W1hi[i] = hi;
    g_W1lo[i] = lo;
}

// ---------------------------------------------------------------------------
// K1: y[8192][128] = x[8192][512] @ W1'[128][512]^T via tf32 MMA + hi/lo split
// Block: 64 pts x 128 N, BK=16, 256 threads (8 warps, each 32x32)
// smem stride 20 floats -> conflict-free fragment loads
// ---------------------------------------------------------------------------
__global__ void __launch_bounds__(256) k1_gemm1(const float* __restrict__ x) {
    __shared__ float sxh[64][20];
    __shared__ float sxl[64][20];
    __shared__ float swh[128][20];
    __shared__ float swl[128][20];

    int tid = threadIdx.x;
    int lane = tid & 31, w = tid >> 5;
    int grp = lane >> 2, tig = lane & 3;
    int m_base = (w >> 2) * 32;     // 0 or 32
    int n_base = (w & 3) * 32;      // 0,32,64,96
    int p0 = blockIdx.x * 64;

    float acc[2][4][4];
#pragma unroll
    for (int r = 0; r < 2; r++)
#pragma unroll
        for (int j = 0; j < 4; j++)
#pragma unroll
            for (int q = 0; q < 4; q++) acc[r][j][q] = 0.f;

    int xrow = tid >> 2;            // 0..63
    int cseg = (tid & 3) * 4;       // 0,4,8,12

    for (int t = 0; t < 32; t++) {
        int k0 = t * 16;
        // load x tile, split hi/lo
        {
            float4 v = *reinterpret_cast<const float4*>(&x[(p0 + xrow) * 512 + k0 + cseg]);
            float h0 = tf32_rna(v.x), h1 = tf32_rna(v.y), h2 = tf32_rna(v.z), h3 = tf32_rna(v.w);
            float4 hv = make_float4(h0, h1, h2, h3);
            float4 lv = make_float4(tf32_rna(v.x - h0), tf32_rna(v.y - h1),
                                    tf32_rna(v.z - h2), tf32_rna(v.w - h3));
            *reinterpret_cast<float4*>(&sxh[xrow][cseg]) = hv;
            *reinterpret_cast<float4*>(&sxl[xrow][cseg]) = lv;
        }
        // load W tiles (pre-split)
#pragma unroll
        for (int rr = 0; rr < 2; rr++) {
            int wrow = (tid >> 2) + rr * 64;
            float4 hv = *reinterpret_cast<const float4*>(&g_W1hi[wrow * 512 + k0 + cseg]);
            float4 lv = *reinterpret_cast<const float4*>(&g_W1lo[wrow * 512 + k0 + cseg]);
            *reinterpret_cast<float4*>(&swh[wrow][cseg]) = hv;
            *reinterpret_cast<float4*>(&swl[wrow][cseg]) = lv;
        }
        __syncthreads();

#pragma unroll
        for (int ks = 0; ks < 16; ks += 8) {
            float ah[2][4], al[2][4], bh[4][2], bl[4][2];
#pragma unroll
            for (int r = 0; r < 2; r++) {
                int mr = m_base + r * 16;
                ah[r][0] = sxh[mr + grp][ks + tig];
                ah[r][1] = sxh[mr + grp + 8][ks + tig];
                ah[r][2] = sxh[mr + grp][ks + tig + 4];
                ah[r][3] = sxh[mr + grp + 8][ks + tig + 4];
                al[r][0] = sxl[mr + grp][ks + tig];
                al[r][1] = sxl[mr + grp + 8][ks + tig];
                al[r][2] = sxl[mr + grp][ks + tig + 4];
                al[r][3] = sxl[mr + grp + 8][ks + tig + 4];
            }
#pragma unroll
            for (int j = 0; j < 4; j++) {
                int nc = n_base + j * 8 + grp;
                bh[j][0] = swh[nc][ks + tig];
                bh[j][1] = swh[nc][ks + tig + 4];
                bl[j][0] = swl[nc][ks + tig];
                bl[j][1] = swl[nc][ks + tig + 4];
            }
#pragma unroll
            for (int r = 0; r < 2; r++)
#pragma unroll
                for (int j = 0; j < 4; j++) {
                    mma_tf32(acc[r][j], ah[r], bh[j]);
                    mma_tf32(acc[r][j], al[r], bh[j]);
                    mma_tf32(acc[r][j], ah[r], bl[j]);
                }
        }
        __syncthreads();
    }

    // epilogue: c-frag rows = grp / grp+8, cols = 2*tig, 2*tig+1
#pragma unroll
    for (int r = 0; r < 2; r++) {
        int prow = p0 + m_base + r * 16 + grp;
#pragma unroll
        for (int j = 0; j < 4; j++) {
            int col = n_base + j * 8 + 2 * tig;
            *reinterpret_cast<float2*>(&g_y[prow * 128 + col]) =
                make_float2(acc[r][j][0], acc[r][j][1]);
            *reinterpret_cast<float2*>(&g_y[(prow + 8) * 128 + col]) =
                make_float2(acc[r][j][2], acc[r][j][3]);
        }
    }
}

// ---------------------------------------------------------------------------
// K2: gather over K=20 neighbors: per (p,m) max/min; block-partial sum/sumsq
// ---------------------------------------------------------------------------
__global__ void __launch_bounds__(256) k2_gather(const int* __restrict__ idx) {
    __shared__ int   sidx[4][20];
    __shared__ float red[2][256];
    int tid = threadIdx.x;
    int m = tid & 63, slot = tid >> 6;
    float fs = 0.f, fq = 0.f;
    int pbase = blockIdx.x * 32;

    for (int i = 0; i < 8; i++) {
        int p = pbase + i * 4 + slot;
        if (m < 20) sidx[slot][m] = idx[p * 20 + m];
        __syncthreads();
        float y2 = g_y[p * 128 + 64 + m];
        int rowb = (p & ~1023) * 128;     // batch base row * 128
        float vmax = -1e30f, vmin = 1e30f;
#pragma unroll
        for (int k = 0; k < 20; k++) {
            int g = sidx[slot][k];
            float v = g_y[rowb + g * 128 + m] + y2;
            fs += v;
            fq += v * v;
            vmax = fmaxf(vmax, v);
            vmin = fminf(vmin, v);
        }
        g_hmax[p * 64 + m] = vmax;
        g_hmin[p * 64 + m] = vmin;
        __syncthreads();
    }
    red[0][tid] = fs;
    red[1][tid] = fq;
    __syncthreads();
    if (tid < 64) {
        float s = red[0][tid] + red[0][tid + 64] + red[0][tid + 128] + red[0][tid + 192];
        float q = red[1][tid] + red[1][tid + 64] + red[1][tid + 128] + red[1][tid + 192];
        g_part1[blockIdx.x * 128 + tid] = s;
        g_part1[blockIdx.x * 128 + 64 + tid] = q;
    }
}

// ---------------------------------------------------------------------------
// K3: finalize BN1 scale/bias — 1024 threads: 8 chunks x 128 cols
// ---------------------------------------------------------------------------
__global__ void __launch_bounds__(1024) k3_stats1(const float* __restrict__ gamma1,
                                                  const float* __restrict__ beta1) {
    __shared__ float red[1024];
    __shared__ float tot[128];
    int tid = threadIdx.x;
    int col = tid & 127, chunk = tid >> 7;   // 8 chunks of 32 rows
    float s = 0.f;
#pragma unroll 4
    for (int r = 0; r < 32; r++)
        s += g_part1[(chunk * 32 + r) * 128 + col];
    red[tid] = s;
    __syncthreads();
    if (tid < 128) {
        float t = 0.f;
#pragma unroll
        for (int c = 0; c < 8; c++) t += red[tid + 128 * c];
        tot[tid] = t;
    }
    __syncthreads();
    if (tid < 64) {
        float inv = 1.f / (float)CNT1;
        float mu = tot[tid] * inv;
        float var = tot[tid + 64] * inv - mu * mu;
        float sc = gamma1[tid] * rsqrtf(var + EPS);
        g_bn1[tid] = sc;
        g_bn1[64 + tid] = beta1[tid] - mu * sc;
    }
}

// ---------------------------------------------------------------------------
// K4: v = leaky(bn1(select(max/min))) fused into GEMM2 + BN2 partial stats
// ---------------------------------------------------------------------------
__global__ void __launch_bounds__(256) k4_gemm2(const float* __restrict__ W2,
                                                float* __restrict__ out) {
    __shared__ float sh[64][65];   // [m][pt]
    __shared__ float sw[64][65];   // [m][dd]
    __shared__ float sbn[128];
    __shared__ float reds[16 * 64];
    __shared__ float redq[16 * 64];
    int tid = threadIdx.x;
    int tx = tid & 15, ty = tid >> 4;
    int d0 = blockIdx.x * 64, p0 = blockIdx.y * 64;

    if (tid < 128) sbn[tid] = g_bn1[tid];
    __syncthreads();

#pragma unroll
    for (int i = 0; i < 16; i++) {
        int e = tid + i * 256;
        int pt = e >> 6, m = e & 63;
        float sc = sbn[m], bi = sbn[64 + m];
        float h = (sc >= 0.f) ? g_hmax[(p0 + pt) * 64 + m] : g_hmin[(p0 + pt) * 64 + m];
        float v = sc * h + bi;
        sh[m][pt] = fmaxf(v, 0.2f * v);           // leaky
    }
#pragma unroll
    for (int i = 0; i < 16; i++) {
        int e = tid + i * 256;
        int dd = e >> 6, m = e & 63;
        sw[m][dd] = W2[(d0 + dd) * 64 + m];
    }
    __syncthreads();

    float acc[4][4];
#pragma unroll
    for (int r = 0; r < 4; r++)
#pragma unroll
        for (int j = 0; j < 4; j++) acc[r][j] = 0.f;

#pragma unroll
    for (int kk = 0; kk < 64; kk++) {
        float a[4], b[4];
#pragma unroll
        for (int r = 0; r < 4; r++) a[r] = sh[kk][ty + 16 * r];
#pragma unroll
        for (int j = 0; j < 4; j++) b[j] = sw[kk][tx + 16 * j];
#pragma unroll
        for (int r = 0; r < 4; r++)
#pragma unroll
            for (int j = 0; j < 4; j++) acc[r][j] += a[r] * b[j];
    }

    float ps[4] = {0.f, 0.f, 0.f, 0.f}, pq[4] = {0.f, 0.f, 0.f, 0.f};
#pragma unroll
    for (int r = 0; r < 4; r++) {
        int p = p0 + ty + 16 * r;
#pragma unroll
        for (int j = 0; j < 4; j++) {
            float v = acc[r][j];
            out[p * 512 + d0 + tx + 16 * j] = v;
            ps[j] += v;
            pq[j] += v * v;
        }
    }
#pragma unroll
    for (int j = 0; j < 4; j++) {
        reds[ty * 64 + tx + 16 * j] = ps[j];
        redq[ty * 64 + tx + 16 * j] = pq[j];
    }
    __syncthreads();
    if (tid < 64) {
        float s = 0.f, q = 0.f;
#pragma unroll
        for (int t = 0; t < 16; t++) {
            s += reds[t * 64 + tid];
            q += redq[t * 64 + tid];
        }
        g_p2s[blockIdx.y * 512 + d0 + tid] = s;
        g_p2q[blockIdx.y * 512 + d0 + tid] = q;
    }
}

// ---------------------------------------------------------------------------
// K5: finalize BN2 — 2 blocks x 1024 threads: 4 chunks x 256 channels
// ---------------------------------------------------------------------------
__global__ void __launch_bounds__(1024) k5_stats2(const float* __restrict__ gamma2,
                                                   const float* __restrict__ beta2) {
    __shared__ float ss[1024];
    __shared__ float sq[1024];
    int tid = threadIdx.x;
    int ch = blockIdx.x * 256 + (tid & 255);
    int chunk = tid >> 8;                     // 4 chunks of 32 rows
    float s = 0.f, q = 0.f;
#pragma unroll 4
    for (int r = 0; r < 32; r++) {
        int row = chunk * 32 + r;
        s += g_p2s[row * 512 + ch];
        q += g_p2q[row * 512 + ch];
    }
    ss[tid] = s;
    sq[tid] = q;
    __syncthreads();
    if (tid < 256) {
        float ts = 0.f, tq = 0.f;
#pragma unroll
        for (int c = 0; c < 4; c++) {
            ts += ss[tid + 256 * c];
            tq += sq[tid + 256 * c];
        }
        float inv = 1.f / (float)CNT2;
        float mu = ts * inv;
        float var = tq * inv - mu * mu;
        float sc = gamma2[ch] * rsqrtf(var + EPS);
        g_bn2[ch] = sc;
        g_bn2[512 + ch] = beta2[ch] - mu * sc;
    }
}

// ---------------------------------------------------------------------------
// K6: in-place affine + leaky on out (float4 vectorized)
// ---------------------------------------------------------------------------
__global__ void __launch_bounds__(256) k6_final(float* __restrict__ out) {
    int i = blockIdx.x * 256 + threadIdx.x;   // float4 index, 1048576 total
    float4 v = reinterpret_cast<float4*>(out)[i];
    int d = (i * 4) & 511;
    float s0 = g_bn2[d],       s1 = g_bn2[d + 1],   s2 = g_bn2[d + 2],   s3 = g_bn2[d + 3];
    float b0 = g_bn2[512 + d], b1 = g_bn2[513 + d], b2 = g_bn2[514 + d], b3 = g_bn2[515 + d];
    float t0 = s0 * v.x + b0;
    float t1 = s1 * v.y + b1;
    float t2 = s2 * v.z + b2;
    float t3 = s3 * v.w + b3;
    v.x = fmaxf(t0, 0.2f * t0);
    v.y = fmaxf(t1, 0.2f * t1);
    v.z = fmaxf(t2, 0.2f * t2);
    v.w = fmaxf(t3, 0.2f * t3);
    reinterpret_cast<float4*>(out)[i] = v;
}

// ---------------------------------------------------------------------------
extern "C" void kernel_launch(void* const* d_in, const int* in_sizes, int n_in,
                              void* d_out, int out_size) {
    const float* x      = (const float*)d_in[0];
    const int*   idx    = (const int*)  d_in[1];
    const float* W1     = (const float*)d_in[2];
    const float* gamma1 = (const float*)d_in[3];
    const float* beta1  = (const float*)d_in[4];
    const float* W2     = (const float*)d_in[5];
    const float* gamma2 = (const float*)d_in[6];
    const float* beta2  = (const float*)d_in[7];
    float* out = (float*)d_out;

    k0_prepw<<<256, 256>>>(W1);
    k1_gemm1<<<128, 256>>>(x);
    k2_gather<<<256, 256>>>(idx);
    k3_stats1<<<1, 1024>>>(gamma1, beta1);
    k4_gemm2<<<dim3(8, 128), 256>>>(W2, out);
    k5_stats2<<<2, 1024>>>(gamma2, beta2);
    k6_final<<<4096, 256>>>(out);
}